// round 5
// baseline (speedup 1.0000x reference)
#include <cuda_runtime.h>
#include <cstdint>

// Problem constants (fixed shapes from reference)
#define BB 2
#define TT 2048
#define DD 512
#define HH 8
#define DH 64
#define SCALE 0.125f   // 64^-0.5

// Scratch: Qp[b,q,h,d] (conv folded into query, scale folded), bias dot per (b,q,h)
__device__ float g_Qp[BB * TT * DD];   // 8.4 MB
__device__ float g_bq[BB * TT * HH];

typedef unsigned long long u64;

__device__ __forceinline__ u64 ffma2(u64 a, u64 b, u64 c) {
    u64 d;
    asm("fma.rn.f32x2 %0, %1, %2, %3;" : "=l"(d) : "l"(a), "l"(b), "l"(c));
    return d;
}
__device__ __forceinline__ float2 unpk(u64 a) {
    float2 r;
    asm("mov.b64 {%0,%1}, %2;" : "=f"(r.x), "=f"(r.y) : "l"(a));
    return r;
}
__device__ __forceinline__ u64 pk2(float x) {
    u64 r;
    asm("mov.b64 %0, {%1,%1};" : "=l"(r) : "f"(x));
    return r;
}
__device__ __forceinline__ uint32_t smem_u32(const void* p) {
    uint32_t a;
    asm("{ .reg .u64 t; cvta.to.shared.u64 t, %1; cvt.u32.u64 %0, t; }"
        : "=r"(a) : "l"(p));
    return a;
}
__device__ __forceinline__ void cp16(uint32_t dst, const void* src) {
    asm volatile("cp.async.cg.shared.global [%0], [%1], 16;" :: "r"(dst), "l"(src));
}
#define CP_COMMIT()  asm volatile("cp.async.commit_group;")
#define CP_WAIT(N)   asm volatile("cp.async.wait_group %0;" :: "n"(N))

// ---------------------------------------------------------------------------
// Kernel 1: Qp[row, h*64+d] = SCALE * sum_j query[row, h*64+j] * conv_w[h*64+j, d]
//           bq[row, h]      = SCALE * sum_j query[row, h*64+j] * conv_b[h*64+j]
// ---------------------------------------------------------------------------
#define TQ1 16
__global__ __launch_bounds__(256) void prep_kernel(
    const float* __restrict__ query,
    const float* __restrict__ conv_w,
    const float* __restrict__ conv_b)
{
    __shared__ __align__(16) float q_sh[TQ1][DD];   // 32 KB
    const int q0 = blockIdx.x * TQ1;                // row base in [0, B*T)
    const int t  = threadIdx.x;

    const float4* qg = (const float4*)(query + (size_t)q0 * DD);
    float4* qs = (float4*)&q_sh[0][0];
    #pragma unroll
    for (int i = 0; i < TQ1 * DD / 4 / 256; ++i)    // 8
        qs[t + i * 256] = qg[t + i * 256];
    __syncthreads();

    // bias dot terms (conv_b is zero in this dataset, but keep it general)
    if (t < TQ1 * HH) {                             // 128 threads
        int q = t >> 3, h = t & 7;
        float acc = 0.f;
        #pragma unroll
        for (int j = 0; j < DH; ++j)
            acc += q_sh[q][h * DH + j] * __ldg(conv_b + h * DH + j);
        g_bq[(q0 + q) * HH + h] = SCALE * acc;
    }

    #pragma unroll 1
    for (int cc = 0; cc < 2; ++cc) {
        int c = t + cc * 256;                       // output column 0..511
        int h = c >> 6;
        float W[DH];
        #pragma unroll
        for (int j = 0; j < DH; ++j)
            W[j] = __ldg(conv_w + (h * DH + j) * DH + (c & 63));
        #pragma unroll 1
        for (int q = 0; q < TQ1; ++q) {
            const float4* qr = (const float4*)&q_sh[q][h * DH];
            float acc = 0.f;
            #pragma unroll
            for (int i = 0; i < 16; ++i) {
                float4 v = qr[i];
                acc += W[4*i+0] * v.x + W[4*i+1] * v.y
                     + W[4*i+2] * v.z + W[4*i+3] * v.w;
            }
            g_Qp[(size_t)(q0 + q) * DD + c] = SCALE * acc;
        }
    }
}

// ---------------------------------------------------------------------------
// Kernel 2: fused scores + head-softmax + context, single-pass per key.
// Block = 256 threads = 16 q-rows x 8 heads x 2 d-halves.
// Lane layout: h = bits[2:0] (softmax shuffle group), e = bit 3 (d-half).
// Per key: load V-half ONCE into registers, dot-product (16 ffma2),
// 4-shuffle softmax over heads, context update (16 ffma2) reusing the same
// V registers. Halves LDS traffic vs the two-phase version.
// V tiles (64 keys x 64 d) double-buffered in SMEM via cp.async.
// ---------------------------------------------------------------------------
#define TQ 16
#define KT 64
#define NTILES (TT / KT)
__global__ __launch_bounds__(256, 2) void attn_kernel(
    const float* __restrict__ value,
    float* __restrict__ out)
{
    __shared__ __align__(16) float v_sh[2][KT * DH];   // 2 x 16 KB
    const int b  = blockIdx.y;
    const int q0 = blockIdx.x * TQ;
    const int t  = threadIdx.x;
    const int h  = t & 7;           // softmax group (8 heads)
    const int e  = (t >> 3) & 1;    // d-half
    const int ql = t >> 4;          // 0..15
    const int row = b * TT + q0 + ql;

    // This thread's half of Qp[row, h, :]: 32 floats = 16 packed f32x2
    u64 qp2[16];
    {
        const longlong2* qpg =
            (const longlong2*)(g_Qp + (size_t)row * DD + h * DH + e * 32);
        #pragma unroll
        for (int i = 0; i < 8; ++i) {
            longlong2 v = qpg[i];
            qp2[2*i]     = (u64)v.x;
            qp2[2*i + 1] = (u64)v.y;
        }
    }
    const float ebq = __expf(g_bq[row * HH + h]);   // bias folded into exp

    u64 ctx2[16];
    #pragma unroll
    for (int i = 0; i < 16; ++i) ctx2[i] = 0ULL;

    const char* vbase = (const char*)(value + (size_t)b * TT * DH);
    const uint32_t sb[2] = { smem_u32(&v_sh[0][0]), smem_u32(&v_sh[1][0]) };

    // Prologue: stage tile 0 (16 KB: 4 x 16B per thread)
    {
        const char* src = vbase + t * 16;
        #pragma unroll
        for (int i = 0; i < 4; ++i)
            cp16(sb[0] + t * 16 + i * 4096, src + i * 4096);
        CP_COMMIT();
    }

    #pragma unroll 1
    for (int tile = 0; tile < NTILES; ++tile) {
        // Prefetch next tile into the other buffer
        if (tile + 1 < NTILES) {
            const char* src = vbase + (size_t)(tile + 1) * (KT * DH * 4) + t * 16;
            uint32_t dbuf = sb[(tile + 1) & 1];
            #pragma unroll
            for (int i = 0; i < 4; ++i)
                cp16(dbuf + t * 16 + i * 4096, src + i * 4096);
            CP_COMMIT();
            CP_WAIT(1);     // current tile's group done
        } else {
            CP_WAIT(0);
        }
        __syncthreads();

        const longlong2* Vs = (const longlong2*)&v_sh[tile & 1][0];

        #pragma unroll 1
        for (int tt0 = 0; tt0 < KT; tt0 += 8) {
            #pragma unroll
            for (int j = 0; j < 8; ++j) {
                const longlong2* vr = Vs + (tt0 + j) * 16 + e * 8;

                // Load this key's V-half once; keep live through softmax.
                u64 vv[16];
                u64 a0 = 0ULL, a1 = 0ULL;
                #pragma unroll
                for (int i = 0; i < 8; ++i) {
                    longlong2 vq = vr[i];          // broadcast LDS.128
                    vv[2*i]     = (u64)vq.x;
                    vv[2*i + 1] = (u64)vq.y;
                    a0 = ffma2(qp2[2*i],     vv[2*i],     a0);
                    a1 = ffma2(qp2[2*i + 1], vv[2*i + 1], a1);
                }
                float2 p0 = unpk(a0), p1 = unpk(a1);
                float p = (p0.x + p0.y) + (p1.x + p1.y);
                p += __shfl_xor_sync(0xffffffffu, p, 8);   // fold d-halves

                // Softmax over 8 heads (|s| small: no max-subtract needed)
                float ex = __expf(p) * ebq;
                float sm = ex;
                sm += __shfl_xor_sync(0xffffffffu, sm, 1);
                sm += __shfl_xor_sync(0xffffffffu, sm, 2);
                sm += __shfl_xor_sync(0xffffffffu, sm, 4);
                u64 w2 = pk2(__fdividef(ex, sm));

                // Context update reusing the live V registers
                #pragma unroll
                for (int i = 0; i < 16; ++i)
                    ctx2[i] = ffma2(w2, vv[i], ctx2[i]);
            }
        }
        __syncthreads();   // protect buffer before next prefetch overwrites it
    }

    // out[b, q, h*64 + e*32 + d]
    float* op = out + (size_t)row * DD + h * DH + e * 32;
    #pragma unroll
    for (int i = 0; i < 8; ++i) {
        longlong2 vv;
        vv.x = (long long)ctx2[2*i];
        vv.y = (long long)ctx2[2*i + 1];
        ((longlong2*)op)[i] = vv;
    }
}

extern "C" void kernel_launch(void* const* d_in, const int* in_sizes, int n_in,
                              void* d_out, int out_size) {
    const float* query  = (const float*)d_in[0];   // [2,2048,512]
    const float* value  = (const float*)d_in[1];   // [2,2048,64]
    const float* conv_w = (const float*)d_in[2];   // [512,64,1]
    const float* conv_b = (const float*)d_in[3];   // [512]
    float* out = (float*)d_out;                    // [2,2048,512]

    prep_kernel<<<BB * TT / TQ1, 256>>>(query, conv_w, conv_b);
    dim3 grid(TT / TQ, BB);
    attn_kernel<<<grid, 256>>>(value, out);
}

// round 6
// speedup vs baseline: 1.0564x; 1.0564x over previous
#include <cuda_runtime.h>
#include <cstdint>

// Problem constants (fixed shapes from reference)
#define BB 2
#define TT 2048
#define DD 512
#define HH 8
#define DH 64
#define SCALE 0.125f   // 64^-0.5

// Scratch: Qp[b,q,h,d] (conv folded into query, scale folded), bias dot per (b,q,h)
__device__ float g_Qp[BB * TT * DD];   // 8.4 MB
__device__ float g_bq[BB * TT * HH];

typedef unsigned long long u64;

__device__ __forceinline__ u64 ffma2(u64 a, u64 b, u64 c) {
    u64 d;
    asm("fma.rn.f32x2 %0, %1, %2, %3;" : "=l"(d) : "l"(a), "l"(b), "l"(c));
    return d;
}
__device__ __forceinline__ float2 unpk(u64 a) {
    float2 r;
    asm("mov.b64 {%0,%1}, %2;" : "=f"(r.x), "=f"(r.y) : "l"(a));
    return r;
}
__device__ __forceinline__ u64 pk2(float x) {
    u64 r;
    asm("mov.b64 %0, {%1,%1};" : "=l"(r) : "f"(x));
    return r;
}
__device__ __forceinline__ uint32_t smem_u32(const void* p) {
    uint32_t a;
    asm("{ .reg .u64 t; cvta.to.shared.u64 t, %1; cvt.u32.u64 %0, t; }"
        : "=r"(a) : "l"(p));
    return a;
}
__device__ __forceinline__ void cp16(uint32_t dst, const void* src) {
    asm volatile("cp.async.cg.shared.global [%0], [%1], 16;" :: "r"(dst), "l"(src));
}
#define CP_COMMIT()  asm volatile("cp.async.commit_group;")
#define CP_WAIT(N)   asm volatile("cp.async.wait_group %0;" :: "n"(N))

// ---------------------------------------------------------------------------
// Kernel 1: Qp[row, h*64+d] = SCALE * sum_j query[row, h*64+j] * conv_w[h*64+j, d]
//           bq[row, h]      = SCALE * sum_j query[row, h*64+j] * conv_b[h*64+j]
// ---------------------------------------------------------------------------
#define TQ1 16
__global__ __launch_bounds__(256) void prep_kernel(
    const float* __restrict__ query,
    const float* __restrict__ conv_w,
    const float* __restrict__ conv_b)
{
    __shared__ __align__(16) float q_sh[TQ1][DD];   // 32 KB
    const int q0 = blockIdx.x * TQ1;                // row base in [0, B*T)
    const int t  = threadIdx.x;

    const float4* qg = (const float4*)(query + (size_t)q0 * DD);
    float4* qs = (float4*)&q_sh[0][0];
    #pragma unroll
    for (int i = 0; i < TQ1 * DD / 4 / 256; ++i)    // 8
        qs[t + i * 256] = qg[t + i * 256];
    __syncthreads();

    // bias dot terms (conv_b is zero in this dataset, but keep it general)
    if (t < TQ1 * HH) {                             // 128 threads
        int q = t >> 3, h = t & 7;
        float acc = 0.f;
        #pragma unroll
        for (int j = 0; j < DH; ++j)
            acc += q_sh[q][h * DH + j] * __ldg(conv_b + h * DH + j);
        g_bq[(q0 + q) * HH + h] = SCALE * acc;
    }

    #pragma unroll 1
    for (int cc = 0; cc < 2; ++cc) {
        int c = t + cc * 256;                       // output column 0..511
        int h = c >> 6;
        float W[DH];
        #pragma unroll
        for (int j = 0; j < DH; ++j)
            W[j] = __ldg(conv_w + (h * DH + j) * DH + (c & 63));
        #pragma unroll 1
        for (int q = 0; q < TQ1; ++q) {
            const float4* qr = (const float4*)&q_sh[q][h * DH];
            float acc = 0.f;
            #pragma unroll
            for (int i = 0; i < 16; ++i) {
                float4 v = qr[i];
                acc += W[4*i+0] * v.x + W[4*i+1] * v.y
                     + W[4*i+2] * v.z + W[4*i+3] * v.w;
            }
            g_Qp[(size_t)(q0 + q) * DD + c] = SCALE * acc;
        }
    }
}

// ---------------------------------------------------------------------------
// Kernel 2: fused scores + head-softmax + context.
// Block = 256 threads = 8 q-rows x 8 heads x 4 d-quarters (one q-row / warp).
// Lane layout: h = bits[2:0] (softmax group), e = bits[4:3] (d-quarter).
// Thread (q,h,e) holds 16 floats of Qp and 16 of ctx -> ~72 regs total,
// 3 blocks/SM (24 warps) for latency coverage.
// Score fold: shfl_xor 8,16 over d-quarters; softmax: shfl_xor 1,2,4 over h.
// Two-phase per 4-key chunk (batched softmax = 4 parallel latency chains).
// V tiles (64 keys x 64 d) double-buffered in SMEM via cp.async.
// ---------------------------------------------------------------------------
#define TQ 8
#define KT 64
#define KJ 4
#define NTILES (TT / KT)
__global__ __launch_bounds__(256, 3) void attn_kernel(
    const float* __restrict__ value,
    float* __restrict__ out)
{
    __shared__ __align__(16) float v_sh[2][KT * DH];   // 2 x 16 KB
    const int b  = blockIdx.y;
    const int q0 = blockIdx.x * TQ;
    const int t  = threadIdx.x;
    const int h  = t & 7;           // softmax group (8 heads)
    const int e  = (t >> 3) & 3;    // d-quarter
    const int ql = t >> 5;          // 0..7 (warp id)
    const int row = b * TT + q0 + ql;

    // This thread's quarter of Qp[row, h, :]: 16 floats = 8 packed f32x2
    u64 qp2[8];
    {
        const longlong2* qpg =
            (const longlong2*)(g_Qp + (size_t)row * DD + h * DH + e * 16);
        #pragma unroll
        for (int i = 0; i < 4; ++i) {
            longlong2 v = qpg[i];
            qp2[2*i]     = (u64)v.x;
            qp2[2*i + 1] = (u64)v.y;
        }
    }
    const float ebq = __expf(g_bq[row * HH + h]);   // bias folded into exp

    u64 ctx2[8];
    #pragma unroll
    for (int i = 0; i < 8; ++i) ctx2[i] = 0ULL;

    const char* vbase = (const char*)(value + (size_t)b * TT * DH);
    const uint32_t sb[2] = { smem_u32(&v_sh[0][0]), smem_u32(&v_sh[1][0]) };

    // Prologue: stage tile 0 (16 KB: 4 x 16B per thread)
    {
        const char* src = vbase + t * 16;
        #pragma unroll
        for (int i = 0; i < 4; ++i)
            cp16(sb[0] + t * 16 + i * 4096, src + i * 4096);
        CP_COMMIT();
    }

    #pragma unroll 1
    for (int tile = 0; tile < NTILES; ++tile) {
        // Prefetch next tile into the other buffer
        if (tile + 1 < NTILES) {
            const char* src = vbase + (size_t)(tile + 1) * (KT * DH * 4) + t * 16;
            uint32_t dbuf = sb[(tile + 1) & 1];
            #pragma unroll
            for (int i = 0; i < 4; ++i)
                cp16(dbuf + t * 16 + i * 4096, src + i * 4096);
            CP_COMMIT();
            CP_WAIT(1);     // current tile's group done
        } else {
            CP_WAIT(0);
        }
        __syncthreads();

        const longlong2* Vs = (const longlong2*)&v_sh[tile & 1][0];

        #pragma unroll 1
        for (int tt0 = 0; tt0 < KT; tt0 += KJ) {
            // ---- Phase A: scores for KJ keys (quarter-dot + xor folds) ----
            float s[KJ];
            #pragma unroll
            for (int j = 0; j < KJ; ++j) {
                const longlong2* vr = Vs + (tt0 + j) * 16 + e * 4;
                u64 a0 = 0ULL, a1 = 0ULL;
                #pragma unroll
                for (int i = 0; i < 4; ++i) {
                    longlong2 vq = vr[i];          // 4-address LDS.128
                    a0 = ffma2(qp2[2*i],     (u64)vq.x, a0);
                    a1 = ffma2(qp2[2*i + 1], (u64)vq.y, a1);
                }
                float2 p0 = unpk(a0), p1 = unpk(a1);
                float p = (p0.x + p0.y) + (p1.x + p1.y);
                p += __shfl_xor_sync(0xffffffffu, p, 8);    // fold d-quarters
                p += __shfl_xor_sync(0xffffffffu, p, 16);
                s[j] = p;
            }

            // ---- Softmax over 8 heads (|s| small: no max-subtract) ----
            float w[KJ];
            #pragma unroll
            for (int j = 0; j < KJ; ++j) {
                float ex = __expf(s[j]) * ebq;
                float sm = ex;
                sm += __shfl_xor_sync(0xffffffffu, sm, 1);
                sm += __shfl_xor_sync(0xffffffffu, sm, 2);
                sm += __shfl_xor_sync(0xffffffffu, sm, 4);
                w[j] = __fdividef(ex, sm);
            }

            // ---- Phase B: rank-KJ context update on this d-quarter ----
            #pragma unroll
            for (int j = 0; j < KJ; ++j) {
                u64 w2 = pk2(w[j]);
                const longlong2* vr = Vs + (tt0 + j) * 16 + e * 4;
                #pragma unroll
                for (int i = 0; i < 4; ++i) {
                    longlong2 vq = vr[i];
                    ctx2[2*i]     = ffma2(w2, (u64)vq.x, ctx2[2*i]);
                    ctx2[2*i + 1] = ffma2(w2, (u64)vq.y, ctx2[2*i + 1]);
                }
            }
        }
        __syncthreads();   // protect buffer before next prefetch overwrites it
    }

    // out[b, q, h*64 + e*16 + d]
    float* op = out + (size_t)row * DD + h * DH + e * 16;
    #pragma unroll
    for (int i = 0; i < 4; ++i) {
        longlong2 vv;
        vv.x = (long long)ctx2[2*i];
        vv.y = (long long)ctx2[2*i + 1];
        ((longlong2*)op)[i] = vv;
    }
}

extern "C" void kernel_launch(void* const* d_in, const int* in_sizes, int n_in,
                              void* d_out, int out_size) {
    const float* query  = (const float*)d_in[0];   // [2,2048,512]
    const float* value  = (const float*)d_in[1];   // [2,2048,64]
    const float* conv_w = (const float*)d_in[2];   // [512,64,1]
    const float* conv_b = (const float*)d_in[3];   // [512]
    float* out = (float*)d_out;                    // [2,2048,512]

    prep_kernel<<<BB * TT / TQ1, 256>>>(query, conv_w, conv_b);
    dim3 grid(TT / TQ, BB);
    attn_kernel<<<grid, 256>>>(value, out);
}